// round 7
// baseline (speedup 1.0000x reference)
#include <cuda_runtime.h>
#include <cuda_bf16.h>
#include <cstddef>

#define N_MODELS 63

// HBM-bound streaming kernel, 8 samples per thread (2 consecutive int4 per
// row): each warp reads 1KB contiguous per row before hopping to the next
// 8MB-distant row stream -> better DRAM row-buffer locality, 2x per-thread
// MLP, half the loop overhead. __ldcs = evict-first (zero-reuse stream).
// c1/c0 accumulated SEPARATELY, sequentially over m, exactly mirroring the
// reference's two-sum-then-compare fp semantics (rel_err must stay 0.0).
__global__ __launch_bounds__(256, 6)
void vote8_kernel(const int4* __restrict__ votes,
                  const float* __restrict__ weights,
                  float4* __restrict__ out,
                  int n4)   // n4 = n/4 int4-groups per row
{
    __shared__ float sw[N_MODELS];
    if (threadIdx.x < N_MODELS) sw[threadIdx.x] = weights[threadIdx.x];
    __syncthreads();

    int n8 = n4 >> 1;   // pairs of int4 per row
    int i = blockIdx.x * blockDim.x + threadIdx.x;
    int stride = gridDim.x * blockDim.x;

    for (; i < n8; i += stride) {
        float c1[8] = {0.f, 0.f, 0.f, 0.f, 0.f, 0.f, 0.f, 0.f};
        float c0[8] = {0.f, 0.f, 0.f, 0.f, 0.f, 0.f, 0.f, 0.f};
        const int4* p = votes + 2 * (size_t)i;
#pragma unroll
        for (int m = 0; m < N_MODELS; m++) {
            int4 va = __ldcs(p);
            int4 vb = __ldcs(p + 1);
            p += n4;
            float wm = sw[m];
            // +0.0f adds are exact: preserves the reference's per-branch sums.
            c1[0] += va.x ? wm : 0.0f;  c0[0] += va.x ? 0.0f : wm;
            c1[1] += va.y ? wm : 0.0f;  c0[1] += va.y ? 0.0f : wm;
            c1[2] += va.z ? wm : 0.0f;  c0[2] += va.z ? 0.0f : wm;
            c1[3] += va.w ? wm : 0.0f;  c0[3] += va.w ? 0.0f : wm;
            c1[4] += vb.x ? wm : 0.0f;  c0[4] += vb.x ? 0.0f : wm;
            c1[5] += vb.y ? wm : 0.0f;  c0[5] += vb.y ? 0.0f : wm;
            c1[6] += vb.z ? wm : 0.0f;  c0[6] += vb.z ? 0.0f : wm;
            c1[7] += vb.w ? wm : 0.0f;  c0[7] += vb.w ? 0.0f : wm;
        }
        float4 oa, ob;
        oa.x = (c1[0] > c0[0]) ? 1.0f : 0.0f;
        oa.y = (c1[1] > c0[1]) ? 1.0f : 0.0f;
        oa.z = (c1[2] > c0[2]) ? 1.0f : 0.0f;
        oa.w = (c1[3] > c0[3]) ? 1.0f : 0.0f;
        ob.x = (c1[4] > c0[4]) ? 1.0f : 0.0f;
        ob.y = (c1[5] > c0[5]) ? 1.0f : 0.0f;
        ob.z = (c1[6] > c0[6]) ? 1.0f : 0.0f;
        ob.w = (c1[7] > c0[7]) ? 1.0f : 0.0f;
        __stcs(&out[2 * (size_t)i], oa);
        __stcs(&out[2 * (size_t)i + 1], ob);
    }
}

// Scalar tail for samples not covered by the 8-wide kernel (n % 8).
// For n = 2e6 this never runs; kept for generality.
__global__ void vote_tail_kernel(const int* __restrict__ votes,
                                 const float* __restrict__ weights,
                                 float* __restrict__ out,
                                 int n, int start) {
    int i = start + blockIdx.x * blockDim.x + threadIdx.x;
    if (i >= n) return;
    float c1 = 0.f, c0 = 0.f;
    for (int m = 0; m < N_MODELS; m++) {
        float wm = weights[m];
        if (votes[(size_t)m * (size_t)n + (size_t)i]) c1 += wm; else c0 += wm;
    }
    out[i] = (c1 > c0) ? 1.0f : 0.0f;
}

extern "C" void kernel_launch(void* const* d_in, const int* in_sizes, int n_in,
                              void* d_out, int out_size) {
    // Bind inputs by SIZE: weights has exactly N_MODELS elements.
    const int* votes = nullptr;
    const float* weights = nullptr;
    long long votes_elems = 0;
    for (int k = 0; k < n_in; k++) {
        if (in_sizes[k] == N_MODELS) {
            weights = (const float*)d_in[k];
        } else {
            votes = (const int*)d_in[k];
            votes_elems = in_sizes[k];
        }
    }
    float* out = (float*)d_out;   // float32 0/1 (established round 4)

    int n = (int)(votes_elems / N_MODELS);   // samples (2e6)
    int n4 = n / 4;                          // int4 groups per row
    int n8 = n4 / 2;                         // 8-sample groups per thread
    int covered = n8 * 8;

    if (n8 > 0) {
        const int threads = 256;
        int blocks = (n8 + threads - 1) / threads;   // 977 for n=2e6
        vote8_kernel<<<blocks, threads>>>((const int4*)votes, weights,
                                          (float4*)out, n4);
    }
    if (covered < n) {
        int rem = n - covered;
        vote_tail_kernel<<<(rem + 127) / 128, 128>>>(votes, weights, out, n,
                                                     covered);
    }
}

// round 8
// speedup vs baseline: 1.1870x; 1.1870x over previous
#include <cuda_runtime.h>
#include <cuda_bf16.h>
#include <cstddef>

#define N_MODELS 63

// Best-measured configuration (R4): 4 samples/thread via int4, plain global
// loads, no launch_bounds (47 regs, occ ~54% — measured DRAM 81.8%, the
// highest of all variants; __ldcs and higher occupancy were neutral, 8-wide
// regressed to 69.6% DRAM by halving the number of concurrent load streams).
// This problem is DRAM-scheduler-saturated: 512MB mandatory traffic at
// ~6.5TB/s achieved = ~79us kernel floor.
//
// c1/c0 accumulated SEPARATELY, sequentially over m, exactly mirroring the
// reference's two-sum-then-compare fp semantics. Do NOT reorder the sums:
// one flipped marginal sample = 1e-3 rel_err = fail (threshold is strict <).
__global__ void vote4_kernel(const int4* __restrict__ votes,
                             const float* __restrict__ weights,
                             float4* __restrict__ out,
                             int n4) {
    __shared__ float sw[N_MODELS];
    if (threadIdx.x < N_MODELS) sw[threadIdx.x] = weights[threadIdx.x];
    __syncthreads();

    int i = blockIdx.x * blockDim.x + threadIdx.x;
    int stride = gridDim.x * blockDim.x;

    for (; i < n4; i += stride) {
        float c1x = 0.f, c1y = 0.f, c1z = 0.f, c1w = 0.f;
        float c0x = 0.f, c0y = 0.f, c0z = 0.f, c0w = 0.f;
#pragma unroll
        for (int m = 0; m < N_MODELS; m++) {
            int4 v = votes[(size_t)m * (size_t)n4 + (size_t)i];
            float wm = sw[m];
            if (v.x) c1x += wm; else c0x += wm;
            if (v.y) c1y += wm; else c0y += wm;
            if (v.z) c1z += wm; else c0z += wm;
            if (v.w) c1w += wm; else c0w += wm;
        }
        float4 o;
        o.x = (c1x > c0x) ? 1.0f : 0.0f;
        o.y = (c1y > c0y) ? 1.0f : 0.0f;
        o.z = (c1z > c0z) ? 1.0f : 0.0f;
        o.w = (c1w > c0w) ? 1.0f : 0.0f;
        out[i] = o;
    }
}

// Scalar tail (never runs for n = 2e6, kept for generality).
__global__ void vote_tail_kernel(const int* __restrict__ votes,
                                 const float* __restrict__ weights,
                                 float* __restrict__ out,
                                 int n, int start) {
    int i = start + blockIdx.x * blockDim.x + threadIdx.x;
    if (i >= n) return;
    float c1 = 0.f, c0 = 0.f;
    for (int m = 0; m < N_MODELS; m++) {
        float wm = weights[m];
        if (votes[(size_t)m * (size_t)n + (size_t)i]) c1 += wm; else c0 += wm;
    }
    out[i] = (c1 > c0) ? 1.0f : 0.0f;
}

extern "C" void kernel_launch(void* const* d_in, const int* in_sizes, int n_in,
                              void* d_out, int out_size) {
    // Bind inputs by SIZE: weights has exactly N_MODELS elements; votes is
    // the big matrix. Derive n from the votes element count.
    const int* votes = nullptr;
    const float* weights = nullptr;
    long long votes_elems = 0;
    for (int k = 0; k < n_in; k++) {
        if (in_sizes[k] == N_MODELS) {
            weights = (const float*)d_in[k];
        } else {
            votes = (const int*)d_in[k];
            votes_elems = in_sizes[k];
        }
    }
    float* out = (float*)d_out;   // float32 0/1 output (established round 4)

    int n = (int)(votes_elems / N_MODELS);   // samples (2e6)
    int n4 = n / 4;
    int tail_start = n4 * 4;

    if (n4 > 0) {
        const int threads = 256;
        int blocks = (n4 + threads - 1) / threads;   // 1954 for n=2e6
        vote4_kernel<<<blocks, threads>>>((const int4*)votes, weights,
                                          (float4*)out, n4);
    }
    if (tail_start < n) {
        int rem = n - tail_start;
        vote_tail_kernel<<<(rem + 127) / 128, 128>>>(votes, weights, out, n,
                                                     tail_start);
    }
}